// round 5
// baseline (speedup 1.0000x reference)
#include <cuda_runtime.h>
#include <cstdint>

// Problem constants
#define NB      2
#define N_SRC   131072
#define N_DST   131072
#define E_CNT   524288
#define FDIM    64
#define F4      (FDIM / 4)     // 16 float4 per feature row
#define EPS_F   1e-8f

#define SCAN_BLK   1024
#define SCAN_NBLK  (N_DST / SCAN_BLK)   // 128

// ---------------- scratch (__device__ globals; no allocation) ----------------
__device__ int   g_cnt[N_DST];      // edges per dst
__device__ int   g_cur[N_DST];      // fill cursor per dst
__device__ int   g_incl[N_DST];     // block-local inclusive scan of cnt
__device__ int   g_bsum[SCAN_NBLK]; // per-block totals
__device__ int   g_boff[SCAN_NBLK]; // exclusive scan of block totals
__device__ int   g_ssrc[E_CNT];     // src sorted by dst
__device__ float g_sw[E_CNT];       // weights sorted by dst

// ---------------------------------------------------------------------------
// K0: zero cnt + cur
// ---------------------------------------------------------------------------
__global__ void zero_kernel() {
    int i = blockIdx.x * blockDim.x + threadIdx.x;
    if (i < N_DST) { g_cnt[i] = 0; g_cur[i] = 0; }
}

// ---------------------------------------------------------------------------
// K1: histogram of dst (int32 indices)
// ---------------------------------------------------------------------------
__global__ void hist_kernel(const int* __restrict__ dst) {
    int e = blockIdx.x * blockDim.x + threadIdx.x;
    if (e < E_CNT) {
        int d = dst[e] & (N_DST - 1);
        atomicAdd(&g_cnt[d], 1);
    }
}

// ---------------------------------------------------------------------------
// K2: per-block inclusive scan of cnt (1024 elems/block, 128 blocks)
// ---------------------------------------------------------------------------
__global__ void scanA_kernel() {
    __shared__ int sh[SCAN_BLK];
    int tid = threadIdx.x;
    int i = blockIdx.x * SCAN_BLK + tid;
    sh[tid] = g_cnt[i];
    __syncthreads();
#pragma unroll
    for (int ofs = 1; ofs < SCAN_BLK; ofs <<= 1) {
        int t = (tid >= ofs) ? sh[tid - ofs] : 0;
        __syncthreads();
        sh[tid] += t;
        __syncthreads();
    }
    g_incl[i] = sh[tid];
    if (tid == SCAN_BLK - 1) g_bsum[blockIdx.x] = sh[tid];
}

// ---------------------------------------------------------------------------
// K3: exclusive scan of 128 block sums (single block)
// ---------------------------------------------------------------------------
__global__ void scanB_kernel() {
    __shared__ int sh[SCAN_NBLK];
    int tid = threadIdx.x;   // 0..127
    int v = g_bsum[tid];
    sh[tid] = v;
    __syncthreads();
#pragma unroll
    for (int ofs = 1; ofs < SCAN_NBLK; ofs <<= 1) {
        int t = (tid >= ofs) ? sh[tid - ofs] : 0;
        __syncthreads();
        sh[tid] += t;
        __syncthreads();
    }
    g_boff[tid] = sh[tid] - v;   // exclusive
}

__device__ __forceinline__ int dst_offset(int d) {
    return g_incl[d] - g_cnt[d] + g_boff[d >> 10];
}

// ---------------------------------------------------------------------------
// K4: fill CSR slots (src, w) sorted by dst
// ---------------------------------------------------------------------------
__global__ void fill_kernel(const int* __restrict__ src,
                            const int* __restrict__ dst,
                            const float* __restrict__ w) {
    int e = blockIdx.x * blockDim.x + threadIdx.x;
    if (e >= E_CNT) return;
    int d = dst[e] & (N_DST - 1);
    int s = src[e] & (N_SRC - 1);
    int pos = dst_offset(d) + atomicAdd(&g_cur[d], 1);
    if (pos >= 0 && pos < E_CNT) {
        g_ssrc[pos] = s;
        g_sw[pos]   = w[e];
    }
}

// ---------------------------------------------------------------------------
// K5: gather. One warp per dst. lane 0-15 -> batch0 float4 #lane,
// lane 16-31 -> batch1 float4 #(lane-16).
//
// Warp-cooperative index staging: lane j loads (src, w) pair j of the CSR
// segment in one coalesced load; __shfl_sync broadcasts per iteration.
// Shuffles are independent -> all n LDG.128 x-row loads issue back-to-back
// (full MLP), instead of each waiting on a scalar index load.
// ---------------------------------------------------------------------------
__global__ void gather_kernel(const float4* __restrict__ x4,
                              float4* __restrict__ out4) {
    int gtid = blockIdx.x * blockDim.x + threadIdx.x;
    int d    = gtid >> 5;
    int lane = gtid & 31;
    if (d >= N_DST) return;

    int beg = dst_offset(d);
    int n   = g_cnt[d];

    int b  = lane >> 4;
    int fi = lane & 15;
    const float4* xb = x4 + (size_t)b * N_SRC * F4 + fi;

    float4 acc = make_float4(0.f, 0.f, 0.f, 0.f);
    float  sumw = 0.f;

    for (int base = 0; base < n; base += 32) {
        int m = n - base;
        if (m > 32) m = 32;

        // Coalesced cooperative load of up to 32 (src, w) pairs
        int   s_reg = 0;
        float w_reg = 0.f;
        if (lane < m) {
            s_reg = g_ssrc[beg + base + lane];
            w_reg = g_sw[beg + base + lane];
        }

        int i = 0;
        // unroll-by-4 main body: independent shuffles + independent LDG.128s
        for (; i + 4 <= m; i += 4) {
            int   s0 = __shfl_sync(0xffffffffu, s_reg, i + 0);
            int   s1 = __shfl_sync(0xffffffffu, s_reg, i + 1);
            int   s2 = __shfl_sync(0xffffffffu, s_reg, i + 2);
            int   s3 = __shfl_sync(0xffffffffu, s_reg, i + 3);
            float w0 = __shfl_sync(0xffffffffu, w_reg, i + 0);
            float w1 = __shfl_sync(0xffffffffu, w_reg, i + 1);
            float w2 = __shfl_sync(0xffffffffu, w_reg, i + 2);
            float w3 = __shfl_sync(0xffffffffu, w_reg, i + 3);
            float4 v0 = xb[(size_t)s0 * F4];
            float4 v1 = xb[(size_t)s1 * F4];
            float4 v2 = xb[(size_t)s2 * F4];
            float4 v3 = xb[(size_t)s3 * F4];
            acc.x += w0 * v0.x; acc.y += w0 * v0.y; acc.z += w0 * v0.z; acc.w += w0 * v0.w;
            acc.x += w1 * v1.x; acc.y += w1 * v1.y; acc.z += w1 * v1.z; acc.w += w1 * v1.w;
            acc.x += w2 * v2.x; acc.y += w2 * v2.y; acc.z += w2 * v2.z; acc.w += w2 * v2.w;
            acc.x += w3 * v3.x; acc.y += w3 * v3.y; acc.z += w3 * v3.z; acc.w += w3 * v3.w;
            sumw += w0 + w1 + w2 + w3;
        }
        for (; i < m; i++) {
            int   s = __shfl_sync(0xffffffffu, s_reg, i);
            float w = __shfl_sync(0xffffffffu, w_reg, i);
            float4 v = xb[(size_t)s * F4];
            acc.x += w * v.x; acc.y += w * v.y; acc.z += w * v.z; acc.w += w * v.w;
            sumw  += w;
        }
    }

    float inv = (n > 0) ? (1.0f / (sumw + EPS_F)) : 0.0f;
    float4 o = make_float4(acc.x * inv, acc.y * inv, acc.z * inv, acc.w * inv);
    out4[(size_t)b * N_DST * F4 + (size_t)d * F4 + fi] = o;
}

// ---------------------------------------------------------------------------
// Launch. Inputs identified by element count:
//   x: 16,777,216 f32   edge_index: 1,048,576 i32   weights: 524,288 f32
// edge_index is [2, E]: first E = src, next E = dst. Output f32 (B,N_DST,F).
// ---------------------------------------------------------------------------
extern "C" void kernel_launch(void* const* d_in, const int* in_sizes, int n_in,
                              void* d_out, int out_size) {
    const float* x   = nullptr;
    const int*   ei  = nullptr;
    const float* wts = nullptr;

    for (int i = 0; i < n_in; i++) {
        if (in_sizes[i] == NB * N_SRC * FDIM)      x   = (const float*)d_in[i];
        else if (in_sizes[i] == 2 * E_CNT)         ei  = (const int*)d_in[i];
        else if (in_sizes[i] == E_CNT)             wts = (const float*)d_in[i];
    }
    if (!x)   x   = (const float*)d_in[0];
    if (!ei)  ei  = (const int*)d_in[1];
    if (!wts) wts = (const float*)d_in[2];

    const int* src = ei;
    const int* dst = ei + E_CNT;
    float* out = (float*)d_out;

    zero_kernel<<<(N_DST + 255) / 256, 256>>>();
    hist_kernel<<<(E_CNT + 255) / 256, 256>>>(dst);
    scanA_kernel<<<SCAN_NBLK, SCAN_BLK>>>();
    scanB_kernel<<<1, SCAN_NBLK>>>();
    fill_kernel<<<(E_CNT + 255) / 256, 256>>>(src, dst, wts);

    {
        long long total_threads = (long long)N_DST * 32;
        int threads = 256;
        int blocks = (int)((total_threads + threads - 1) / threads);
        gather_kernel<<<blocks, threads>>>((const float4*)x, (float4*)out);
    }
}

// round 6
// speedup vs baseline: 1.3025x; 1.3025x over previous
#include <cuda_runtime.h>
#include <cstdint>

// Problem constants
#define NB      2
#define N_SRC   131072
#define N_DST   131072
#define E_CNT   524288
#define FDIM    64
#define F4      (FDIM / 4)     // 16 float4 per feature row
#define EPS_F   1e-8f

#define SCAN_BLK   1024
#define SCAN_NBLK  (N_DST / SCAN_BLK)   // 128

// ---------------- scratch (__device__ globals; zero-initialized) -------------
// Invariant: every kernel_launch leaves g_cnt and g_cur fully zeroed (gather
// resets them after use), so graph replays see identical starting state.
__device__ int   g_cnt[N_DST];       // edges per dst (hist)
__device__ int   g_cur[N_DST];       // fill cursor per dst
__device__ int   g_excl[N_DST];      // block-local exclusive scan of cnt
__device__ int   g_bsum[SCAN_NBLK];  // per-scan-block totals
__device__ int   g_start[N_DST];     // final CSR start per dst (fill writes)
__device__ int2  g_pair[E_CNT + 8];  // (src, w-bits) sorted by dst (+pad)

// ---------------------------------------------------------------------------
// K1: histogram of dst (g_cnt starts zeroed)
// ---------------------------------------------------------------------------
__global__ void hist_kernel(const int* __restrict__ dst) {
    int e = blockIdx.x * blockDim.x + threadIdx.x;
    if (e < E_CNT) atomicAdd(&g_cnt[dst[e] & (N_DST - 1)], 1);
}

// ---------------------------------------------------------------------------
// K2: per-block EXCLUSIVE scan of cnt (1024/block, 128 blocks), shuffle-based
// ---------------------------------------------------------------------------
__global__ void scanA_kernel() {
    __shared__ int warp_sums[32];
    int tid  = threadIdx.x;
    int i    = blockIdx.x * SCAN_BLK + tid;
    int lane = tid & 31, wid = tid >> 5;

    int v = g_cnt[i];
    // inclusive warp scan
    int s = v;
#pragma unroll
    for (int ofs = 1; ofs < 32; ofs <<= 1) {
        int t = __shfl_up_sync(0xffffffffu, s, ofs);
        if (lane >= ofs) s += t;
    }
    if (lane == 31) warp_sums[wid] = s;
    __syncthreads();
    if (wid == 0) {
        int ws = warp_sums[lane];
        int ss = ws;
#pragma unroll
        for (int ofs = 1; ofs < 32; ofs <<= 1) {
            int t = __shfl_up_sync(0xffffffffu, ss, ofs);
            if (lane >= ofs) ss += t;
        }
        warp_sums[lane] = ss - ws;   // exclusive warp offsets
        if (lane == 31) g_bsum[blockIdx.x] = ss;  // block total
    }
    __syncthreads();
    int incl = s + warp_sums[wid];
    g_excl[i] = incl - v;            // exclusive within block
}

// ---------------------------------------------------------------------------
// K3: fill CSR. Each block first re-scans the 128 block sums in smem
// (replaces the old scanB launch), then scatters (src, w) pairs.
// Also records g_start[d] (the edge that wins slot 0 writes it).
// ---------------------------------------------------------------------------
__global__ void fill_kernel(const int* __restrict__ src,
                            const int* __restrict__ dst,
                            const float* __restrict__ w) {
    __shared__ int sh_boff[SCAN_NBLK];
    int tid = threadIdx.x;
    if (tid < SCAN_NBLK) sh_boff[tid] = g_bsum[tid];
    __syncthreads();
    // Hillis-Steele inclusive scan over 128 elems, then shift to exclusive use
#pragma unroll
    for (int ofs = 1; ofs < SCAN_NBLK; ofs <<= 1) {
        int t = 0;
        if (tid < SCAN_NBLK && tid >= ofs) t = sh_boff[tid - ofs];
        __syncthreads();
        if (tid < SCAN_NBLK) sh_boff[tid] += t;
        __syncthreads();
    }

    int e = blockIdx.x * blockDim.x + tid;
    if (e >= E_CNT) return;
    int d = dst[e] & (N_DST - 1);
    int s = src[e] & (N_SRC - 1);
    int blk = d >> 10;
    int boff = (blk > 0) ? sh_boff[blk - 1] : 0;   // exclusive block offset
    int start = g_excl[d] + boff;
    int old = atomicAdd(&g_cur[d], 1);
    int pos = start + old;
    if (pos >= 0 && pos < E_CNT) {
        g_pair[pos] = make_int2(s, __float_as_int(w[e]));
    }
    if (old == 0) g_start[d] = start;
}

// ---------------------------------------------------------------------------
// K4: gather. One warp per dst. lane 0-15 -> batch0 float4 #lane,
// lane 16-31 -> batch1 float4 #(lane-16).
// Per chunk of 8 edges: 8 INDEPENDENT 8B broadcast pair-loads, then up to 8
// independent LDG.128 x-row loads -> critical path = 1 pair-load + 1 x-load.
// No shuffles. Normalization factored to one multiply at the end.
// Resets g_cnt/g_cur for the next replay.
// ---------------------------------------------------------------------------
__global__ void gather_kernel(const float4* __restrict__ x4,
                              float4* __restrict__ out4) {
    int gtid = blockIdx.x * blockDim.x + threadIdx.x;
    int d    = gtid >> 5;
    int lane = gtid & 31;
    if (d >= N_DST) return;

    int n = g_cnt[d];

    int b  = lane >> 4;
    int fi = lane & 15;
    const float4* xb = x4 + (size_t)b * N_SRC * F4 + fi;

    float4 acc = make_float4(0.f, 0.f, 0.f, 0.f);
    float  sumw = 0.f;

    if (n > 0) {
        const int2* pp = g_pair + g_start[d];
        for (int base = 0; base < n; base += 8) {
            int2 p[8];
#pragma unroll
            for (int j = 0; j < 8; j++) {
                p[j] = (base + j < n) ? pp[base + j] : make_int2(0, 0);
            }
#pragma unroll
            for (int j = 0; j < 8; j++) {
                if (base + j < n) {
                    float w  = __int_as_float(p[j].y);
                    float4 v = xb[(size_t)p[j].x * F4];
                    acc.x += w * v.x;
                    acc.y += w * v.y;
                    acc.z += w * v.z;
                    acc.w += w * v.w;
                    sumw  += w;
                }
            }
        }
    }

    // Reset scratch for next replay (deterministic state across graph replays)
    if (lane == 0) { g_cnt[d] = 0; g_cur[d] = 0; }

    float inv = (n > 0) ? (1.0f / (sumw + EPS_F)) : 0.0f;
    float4 o = make_float4(acc.x * inv, acc.y * inv, acc.z * inv, acc.w * inv);
    out4[(size_t)b * N_DST * F4 + (size_t)d * F4 + fi] = o;
}

// ---------------------------------------------------------------------------
// Launch. Inputs identified by element count:
//   x: 16,777,216 f32   edge_index: 1,048,576 i32   weights: 524,288 f32
// edge_index is [2, E]: first E = src, next E = dst. Output f32 (B,N_DST,F).
// ---------------------------------------------------------------------------
extern "C" void kernel_launch(void* const* d_in, const int* in_sizes, int n_in,
                              void* d_out, int out_size) {
    const float* x   = nullptr;
    const int*   ei  = nullptr;
    const float* wts = nullptr;

    for (int i = 0; i < n_in; i++) {
        if (in_sizes[i] == NB * N_SRC * FDIM)      x   = (const float*)d_in[i];
        else if (in_sizes[i] == 2 * E_CNT)         ei  = (const int*)d_in[i];
        else if (in_sizes[i] == E_CNT)             wts = (const float*)d_in[i];
    }
    if (!x)   x   = (const float*)d_in[0];
    if (!ei)  ei  = (const int*)d_in[1];
    if (!wts) wts = (const float*)d_in[2];

    const int* src = ei;
    const int* dst = ei + E_CNT;
    float* out = (float*)d_out;

    hist_kernel<<<(E_CNT + 255) / 256, 256>>>(dst);
    scanA_kernel<<<SCAN_NBLK, SCAN_BLK>>>();
    fill_kernel<<<(E_CNT + 255) / 256, 256>>>(src, dst, wts);
    {
        long long total_threads = (long long)N_DST * 32;
        int threads = 256;
        int blocks = (int)((total_threads + threads - 1) / threads);
        gather_kernel<<<blocks, threads>>>((const float4*)x, (float4*)out);
    }
}

// round 7
// speedup vs baseline: 1.5051x; 1.1555x over previous
#include <cuda_runtime.h>
#include <cstdint>

// Problem constants
#define NB      2
#define N_SRC   131072
#define N_DST   131072
#define E_CNT   524288
#define FDIM    64
#define F4      (FDIM / 4)     // 16 float4 per feature row
#define EPS_F   1e-8f

#define SCAN_BLK   1024
#define SCAN_NBLK  (N_DST / SCAN_BLK)   // 128

#define D_BLK   64          // destinations per gather block
#define PAIR_CAP 2048       // smem pair-staging capacity (avg need: 256)

// ---------------- scratch (__device__ globals; zero-initialized) -------------
// Invariant: every kernel_launch leaves g_cnt and g_cur zeroed (gather resets
// them), so graph replays see identical starting state.
__device__ int   g_cnt[N_DST];       // edges per dst (hist)
__device__ int   g_cur[N_DST];       // fill cursor per dst
__device__ int   g_excl[N_DST];      // block-local exclusive scan of cnt
__device__ int   g_bsum[SCAN_NBLK];  // per-scan-block totals
__device__ int2  g_pair[E_CNT + 8];  // (src, w-bits) sorted by dst (+pad)

// ---------------------------------------------------------------------------
// K1: histogram of dst (g_cnt starts zeroed)
// ---------------------------------------------------------------------------
__global__ void hist_kernel(const int* __restrict__ dst) {
    int e = blockIdx.x * blockDim.x + threadIdx.x;
    if (e < E_CNT) atomicAdd(&g_cnt[dst[e] & (N_DST - 1)], 1);
}

// ---------------------------------------------------------------------------
// K2: per-block EXCLUSIVE scan of cnt (1024/block, 128 blocks), shuffle-based
// ---------------------------------------------------------------------------
__global__ void scanA_kernel() {
    __shared__ int warp_sums[32];
    int tid  = threadIdx.x;
    int i    = blockIdx.x * SCAN_BLK + tid;
    int lane = tid & 31, wid = tid >> 5;

    int v = g_cnt[i];
    int s = v;
#pragma unroll
    for (int ofs = 1; ofs < 32; ofs <<= 1) {
        int t = __shfl_up_sync(0xffffffffu, s, ofs);
        if (lane >= ofs) s += t;
    }
    if (lane == 31) warp_sums[wid] = s;
    __syncthreads();
    if (wid == 0) {
        int ws = warp_sums[lane];
        int ss = ws;
#pragma unroll
        for (int ofs = 1; ofs < 32; ofs <<= 1) {
            int t = __shfl_up_sync(0xffffffffu, ss, ofs);
            if (lane >= ofs) ss += t;
        }
        warp_sums[lane] = ss - ws;
        if (lane == 31) g_bsum[blockIdx.x] = ss;
    }
    __syncthreads();
    int incl = s + warp_sums[wid];
    g_excl[i] = incl - v;
}

// ---------------------------------------------------------------------------
// K3: fill CSR. Each block re-scans the 128 block sums in smem, then scatters
// (src, w) pairs into the destination-sorted g_pair array.
// ---------------------------------------------------------------------------
__global__ void fill_kernel(const int* __restrict__ src,
                            const int* __restrict__ dst,
                            const float* __restrict__ w) {
    __shared__ int sh_boff[SCAN_NBLK];
    int tid = threadIdx.x;
    if (tid < SCAN_NBLK) sh_boff[tid] = g_bsum[tid];
    __syncthreads();
#pragma unroll
    for (int ofs = 1; ofs < SCAN_NBLK; ofs <<= 1) {
        int t = 0;
        if (tid < SCAN_NBLK && tid >= ofs) t = sh_boff[tid - ofs];
        __syncthreads();
        if (tid < SCAN_NBLK) sh_boff[tid] += t;
        __syncthreads();
    }

    int e = blockIdx.x * blockDim.x + tid;
    if (e >= E_CNT) return;
    int d = dst[e] & (N_DST - 1);
    int s = src[e] & (N_SRC - 1);
    int blk = d >> 10;
    int boff = (blk > 0) ? sh_boff[blk - 1] : 0;
    int pos = g_excl[d] + boff + atomicAdd(&g_cur[d], 1);
    if (pos >= 0 && pos < E_CNT) {
        g_pair[pos] = make_int2(s, __float_as_int(w[e]));
    }
}

// ---------------------------------------------------------------------------
// K4: gather with block-level CSR staging.
// Block = 256 threads, owns D_BLK=64 contiguous dsts whose pair segments form
// ONE contiguous range of g_pair.
//   Phase A: rebuild block-sum scan in smem, compute start[] fence posts for
//            all 65 boundaries from g_excl (cnt = diff of fence posts).
//   Phase B: bulk coalesced copy of the pair range into smem (cap 2048;
//            global fallback if exceeded).
//   Phase C: warp per dst x 8 rounds: pairs via 29-cyc LDS broadcast, x rows
//            via independent LDG.128; one normalization mul; one STG.128.
// Resets g_cnt/g_cur for replay determinism.
// ---------------------------------------------------------------------------
__global__ void gather_kernel(const float4* __restrict__ x4,
                              float4* __restrict__ out4) {
    __shared__ int  sh_boff[SCAN_NBLK];
    __shared__ int  sh_start[D_BLK + 1];
    __shared__ int2 sh_pair[PAIR_CAP];

    int tid = threadIdx.x;
    int d0  = blockIdx.x * D_BLK;

    // Phase A1: scan the 128 block sums (inclusive) in smem
    if (tid < SCAN_NBLK) sh_boff[tid] = g_bsum[tid];
    __syncthreads();
#pragma unroll
    for (int ofs = 1; ofs < SCAN_NBLK; ofs <<= 1) {
        int t = 0;
        if (tid < SCAN_NBLK && tid >= ofs) t = sh_boff[tid - ofs];
        __syncthreads();
        if (tid < SCAN_NBLK) sh_boff[tid] += t;
        __syncthreads();
    }

    // Phase A2: CSR fence posts for the 64 dsts (+1 boundary)
    if (tid <= D_BLK) {
        int d = d0 + tid;
        int start;
        if (d < N_DST) {
            int blk = d >> 10;
            int boff = (blk > 0) ? sh_boff[blk - 1] : 0;
            start = g_excl[d] + boff;
        } else {
            start = E_CNT;
        }
        sh_start[tid] = start;
    }
    // Reset scratch for the next graph replay
    if (tid < D_BLK) { g_cnt[d0 + tid] = 0; g_cur[d0 + tid] = 0; }
    __syncthreads();

    // Phase B: stage the block's contiguous pair range
    int base  = sh_start[0];
    int total = sh_start[D_BLK] - base;
    bool fit  = (total <= PAIR_CAP);
    if (fit) {
        for (int i = tid; i < total; i += 256) sh_pair[i] = g_pair[base + i];
    }
    __syncthreads();

    // Phase C: warp per dst, 8 dsts per warp
    int wid  = tid >> 5;
    int lane = tid & 31;
    int b  = lane >> 4;
    int fi = lane & 15;
    const float4* xb = x4 + (size_t)b * N_SRC * F4 + fi;

#pragma unroll 1
    for (int k = 0; k < D_BLK / 8; k++) {
        int dl = wid * (D_BLK / 8) + k;
        int d  = d0 + dl;
        int s0 = sh_start[dl];
        int n  = sh_start[dl + 1] - s0;

        const int2* pp = fit ? (const int2*)(sh_pair + (s0 - base))
                             : (const int2*)(g_pair + s0);

        float4 acc = make_float4(0.f, 0.f, 0.f, 0.f);
        float  sumw = 0.f;

        for (int bb = 0; bb < n; bb += 8) {
            int2 p[8];
#pragma unroll
            for (int j = 0; j < 8; j++) {
                p[j] = (bb + j < n) ? pp[bb + j] : make_int2(0, 0);
            }
#pragma unroll
            for (int j = 0; j < 8; j++) {
                if (bb + j < n) {
                    float w  = __int_as_float(p[j].y);
                    float4 v = xb[(size_t)p[j].x * F4];
                    acc.x += w * v.x;
                    acc.y += w * v.y;
                    acc.z += w * v.z;
                    acc.w += w * v.w;
                    sumw  += w;
                }
            }
        }

        float inv = (n > 0) ? (1.0f / (sumw + EPS_F)) : 0.0f;
        float4 o = make_float4(acc.x * inv, acc.y * inv, acc.z * inv, acc.w * inv);
        out4[(size_t)b * N_DST * F4 + (size_t)d * F4 + fi] = o;
    }
}

// ---------------------------------------------------------------------------
// Launch. Inputs identified by element count:
//   x: 16,777,216 f32   edge_index: 1,048,576 i32   weights: 524,288 f32
// edge_index is [2, E]: first E = src, next E = dst. Output f32 (B,N_DST,F).
// ---------------------------------------------------------------------------
extern "C" void kernel_launch(void* const* d_in, const int* in_sizes, int n_in,
                              void* d_out, int out_size) {
    const float* x   = nullptr;
    const int*   ei  = nullptr;
    const float* wts = nullptr;

    for (int i = 0; i < n_in; i++) {
        if (in_sizes[i] == NB * N_SRC * FDIM)      x   = (const float*)d_in[i];
        else if (in_sizes[i] == 2 * E_CNT)         ei  = (const int*)d_in[i];
        else if (in_sizes[i] == E_CNT)             wts = (const float*)d_in[i];
    }
    if (!x)   x   = (const float*)d_in[0];
    if (!ei)  ei  = (const int*)d_in[1];
    if (!wts) wts = (const float*)d_in[2];

    const int* src = ei;
    const int* dst = ei + E_CNT;
    float* out = (float*)d_out;

    hist_kernel<<<(E_CNT + 255) / 256, 256>>>(dst);
    scanA_kernel<<<SCAN_NBLK, SCAN_BLK>>>();
    fill_kernel<<<(E_CNT + 255) / 256, 256>>>(src, dst, wts);
    gather_kernel<<<N_DST / D_BLK, 256>>>((const float4*)x, (float4*)out);
}